// round 16
// baseline (speedup 1.0000x reference)
#include <cuda_runtime.h>
#include <cuda_fp16.h>
#include <math.h>

// Problem constants
#define B_   2
#define S_   2048
#define HID_ 2560
#define H_   32
#define KV_  8
#define D_   80
#define G_   4
#define BS_  (B_*S_)      // 4096 total rows

// Scratch (device globals)
__device__ float  g_Q[(size_t)BS_ * H_ * D_];
__device__ float  g_K[(size_t)BS_ * KV_ * D_];
__device__ float  g_V[(size_t)BS_ * KV_ * D_];
__device__ __half g_ctx_h[(size_t)BS_ * H_ * D_];
__device__ __half g_hs_h[(size_t)BS_ * HID_];
__device__ __half g_WqT[(size_t)HID_ * H_ * D_];   // [N=2560][K=2560]
__device__ __half g_WkT[(size_t)KV_ * D_ * HID_];  // [640][2560]
__device__ __half g_WvT[(size_t)KV_ * D_ * HID_];
__device__ __half g_WoT[(size_t)HID_ * H_ * D_];   // [2560][2560]

// ---------------------------------------------------------------------------
// Helpers
// ---------------------------------------------------------------------------
__device__ __forceinline__ unsigned smem_u32(const void* p) {
    return (unsigned)__cvta_generic_to_shared(p);
}
__device__ __forceinline__ void cp_async16(unsigned dst, const void* src) {
    asm volatile("cp.async.cg.shared.global [%0], [%1], 16;\n"
                 :: "r"(dst), "l"(src));
}
#define CP_COMMIT() asm volatile("cp.async.commit_group;\n" ::: "memory")
#define CP_WAIT1()  asm volatile("cp.async.wait_group 1;\n" ::: "memory")
#define CP_WAIT0()  asm volatile("cp.async.wait_group 0;\n" ::: "memory")

__device__ __forceinline__ void mma_f16(float* c, const unsigned* a, const unsigned* b) {
    asm volatile(
        "mma.sync.aligned.m16n8k16.row.col.f32.f16.f16.f32 "
        "{%0,%1,%2,%3}, {%4,%5,%6,%7}, {%8,%9}, {%0,%1,%2,%3};\n"
        : "+f"(c[0]), "+f"(c[1]), "+f"(c[2]), "+f"(c[3])
        : "r"(a[0]), "r"(a[1]), "r"(a[2]), "r"(a[3]), "r"(b[0]), "r"(b[1]));
}

// ---------------------------------------------------------------------------
// Pre-passes: hs -> half ; weights -> transposed half [N][K]
// ---------------------------------------------------------------------------
__global__ void convert_half(const float4* __restrict__ in,
                             __half2* __restrict__ out, int n4)
{
    int i = blockIdx.x * blockDim.x + threadIdx.x;
    if (i < n4) {
        float4 v = in[i];
        out[2 * i]     = __floats2half2_rn(v.x, v.y);
        out[2 * i + 1] = __floats2half2_rn(v.z, v.w);
    }
}

__global__ void transpose_h(const float* __restrict__ W,
                            __half* __restrict__ WT, int Kd, int Nd)
{
    __shared__ float t[32][33];
    int n0 = blockIdx.x * 32, k0 = blockIdx.y * 32;
    int tx = threadIdx.x, ty = threadIdx.y;
    #pragma unroll
    for (int i = 0; i < 4; i++)
        t[ty + i * 8][tx] = W[(size_t)(k0 + ty + i * 8) * Nd + n0 + tx];
    __syncthreads();
    #pragma unroll
    for (int i = 0; i < 4; i++)
        WT[(size_t)(n0 + ty + i * 8) * Kd + k0 + tx] =
            __float2half_rn(t[tx][ty + i * 8]);
}

// ---------------------------------------------------------------------------
// FP16 tensor-core GEMM core (round-11 proven config, untouched):
// 128x128 tile, BK=32 halves, 8 warps, 3-stage cp.async, 2 CTAs/SM.
// Now invoked from PERSISTENT grid-stride wrappers to kill wave quantization.
// ---------------------------------------------------------------------------
#define HSTR 40
#define GSTG (128 * HSTR * 2)                    // halves per stage (A+B)
#define GEMM_SMEM (3 * GSTG * 2)                 // bytes = 61440

__device__ __forceinline__ void gemm_core_h(
    const __half* __restrict__ A, const __half* __restrict__ BT,
    float* __restrict__ C, int N, int K, int bm, int bn)
{
    extern __shared__ __half gsm[];

    const int tid  = threadIdx.x;
    const int lane = tid & 31;
    const int w    = tid >> 5;
    const int wm   = (w >> 2) * 64;
    const int wn   = (w & 3) * 32;
    const int lr   = lane >> 2;
    const int lc   = lane & 3;

    const int l_r = tid >> 2;
    const int l_c = (tid & 3) * 8;

    float acc[4][4][4];
    #pragma unroll
    for (int mi = 0; mi < 4; mi++)
        #pragma unroll
        for (int nj = 0; nj < 4; nj++)
            #pragma unroll
            for (int u = 0; u < 4; u++) acc[mi][nj][u] = 0.f;

    const int T = K / 32;

    auto load_tile = [&](int kt, int buf) {
        __half* as = gsm + buf * GSTG;
        __half* bs = as + 128 * HSTR;
        const __half* ag = A + (size_t)(bm + l_r) * K + kt * 32 + l_c;
        cp_async16(smem_u32(&as[l_r * HSTR + l_c]), ag);
        cp_async16(smem_u32(&as[(l_r + 64) * HSTR + l_c]), ag + (size_t)64 * K);
        const __half* bg = BT + (size_t)(bn + l_r) * K + kt * 32 + l_c;
        cp_async16(smem_u32(&bs[l_r * HSTR + l_c]), bg);
        cp_async16(smem_u32(&bs[(l_r + 64) * HSTR + l_c]), bg + (size_t)64 * K);
    };

    load_tile(0, 0); CP_COMMIT();
    load_tile(1, 1); CP_COMMIT();

    for (int kt = 0; kt < T; kt++) {
        const int buf = kt % 3;
        CP_WAIT1();
        __syncthreads();
        if (kt + 2 < T) load_tile(kt + 2, (kt + 2) % 3);
        CP_COMMIT();

        const __half* as = gsm + buf * GSTG;
        const __half* bs = as + 128 * HSTR;
        #pragma unroll
        for (int ks = 0; ks < 2; ks++) {
            const int ko = ks * 16 + 2 * lc;
            unsigned af[4][4], bf[4][2];
            #pragma unroll
            for (int mi = 0; mi < 4; mi++) {
                int r = wm + mi * 16 + lr;
                af[mi][0] = *(const unsigned*)&as[r * HSTR + ko];
                af[mi][1] = *(const unsigned*)&as[(r + 8) * HSTR + ko];
                af[mi][2] = *(const unsigned*)&as[r * HSTR + ko + 8];
                af[mi][3] = *(const unsigned*)&as[(r + 8) * HSTR + ko + 8];
            }
            #pragma unroll
            for (int nj = 0; nj < 4; nj++) {
                int cn = wn + nj * 8 + lr;
                bf[nj][0] = *(const unsigned*)&bs[cn * HSTR + ko];
                bf[nj][1] = *(const unsigned*)&bs[cn * HSTR + ko + 8];
            }
            #pragma unroll
            for (int mi = 0; mi < 4; mi++)
                #pragma unroll
                for (int nj = 0; nj < 4; nj++)
                    mma_f16(acc[mi][nj], af[mi], bf[nj]);
        }
    }
    // Drain all outstanding cp.async groups before the next tile reuses smem
    CP_WAIT0();
    __syncthreads();

    #pragma unroll
    for (int mi = 0; mi < 4; mi++) {
        int r0 = bm + wm + mi * 16 + lr;
        #pragma unroll
        for (int nj = 0; nj < 4; nj++) {
            int cn = bn + wn + nj * 8 + 2 * lc;
            *(float2*)&C[(size_t)r0 * N + cn] =
                make_float2(acc[mi][nj][0], acc[mi][nj][1]);
            *(float2*)&C[(size_t)(r0 + 8) * N + cn] =
                make_float2(acc[mi][nj][2], acc[mi][nj][3]);
        }
    }
}

// Persistent Wo projection: 640 tiles (20 n x 32 m), grid-stride
__global__ __launch_bounds__(256, 2) void gemm_h_persist(
    const __half* __restrict__ A, const __half* __restrict__ BT,
    float* __restrict__ C)
{
    for (int t = blockIdx.x; t < 640; t += gridDim.x) {
        int bx = t % 20, by = t / 20;
        __syncthreads();   // all warps done with previous tile's smem
        gemm_core_h(A, BT, C, HID_, HID_, by * 128, bx * 128);
    }
}

// Persistent fused QKV projection: 960 tiles (30 x 32), grid-stride
__global__ __launch_bounds__(256, 2) void gemm_qkv_persist(
    const __half* __restrict__ A,
    const __half* __restrict__ WqT, float* __restrict__ Qo,
    const __half* __restrict__ WkT, float* __restrict__ Ko,
    const __half* __restrict__ WvT, float* __restrict__ Vo)
{
    for (int t = blockIdx.x; t < 960; t += gridDim.x) {
        int bx = t % 30, by = t / 30;
        int bm = by * 128;
        __syncthreads();
        if (bx < 20)       gemm_core_h(A, WqT, Qo, HID_,     HID_, bm, bx * 128);
        else if (bx < 25)  gemm_core_h(A, WkT, Ko, KV_ * D_, HID_, bm, (bx - 20) * 128);
        else               gemm_core_h(A, WvT, Vo, KV_ * D_, HID_, bm, (bx - 25) * 128);
    }
}

// ---------------------------------------------------------------------------
// RoPE (in-place, fp32) — K only; Q's rope is fused into attention.
// ---------------------------------------------------------------------------
__global__ void rope_kernel(float* __restrict__ X,
                            const float* __restrict__ cosf,
                            const float* __restrict__ sinf,
                            int nheads, size_t total)
{
    size_t idx = (size_t)blockIdx.x * blockDim.x + threadIdx.x;
    if (idx >= total) return;
    int d = (int)(idx % 40);
    size_t t = idx / 40;
    int head = (int)(t % nheads);
    size_t row = t / nheads;
    int s = (int)(row % S_);

    float* base = X + row * ((size_t)nheads * D_) + (size_t)head * D_;
    float x1 = base[d];
    float x2 = base[d + 40];
    float c1 = cosf[(size_t)s * D_ + d];
    float s1 = sinf[(size_t)s * D_ + d];
    float c2 = cosf[(size_t)s * D_ + d + 40];
    float s2 = sinf[(size_t)s * D_ + d + 40];
    base[d]      = x1 * c1 - x2 * s1;
    base[d + 40] = x2 * c2 + x1 * s2;
}

// ---------------------------------------------------------------------------
// Flash attention (round-15 config, untouched): 4 heads/block, fused Q-rope,
// LPT block order, QK/PV fp16 single-term, register-staged K/V prefetch.
// ---------------------------------------------------------------------------
#define AQH 88
#define VTS 72
#define APH 72
#define AP  68

__device__ __forceinline__ unsigned h2u(__half a, __half b) {
    __half2 p = __halves2half2(a, b);
    return *(unsigned*)&p;
}

__global__ __launch_bounds__(256, 1) void attn_mma4(
    const float* __restrict__ Q, const float* __restrict__ K,
    const float* __restrict__ V, __half* __restrict__ O,
    const float* __restrict__ cosg, const float* __restrict__ sing)
{
    extern __shared__ char smb[];
    __half* Qh[4];
    Qh[0] = (__half*)smb;
    Qh[1] = Qh[0] + 64 * AQH;
    Qh[2] = Qh[1] + 64 * AQH;
    Qh[3] = Qh[2] + 64 * AQH;
    __half* Khh = Qh[3] + 64 * AQH;
    __half* Vt  = Khh + 64 * AQH;
    __half* Pm[4];
    Pm[0] = Vt + 80 * VTS;
    Pm[1] = Pm[0] + 64 * APH;
    Pm[2] = Pm[1] + 64 * APH;
    Pm[3] = Pm[2] + 64 * APH;
    float* Sf[4];
    Sf[0] = (float*)(Pm[3] + 64 * APH);
    Sf[1] = Sf[0] + 64 * AP;
    Sf[2] = Sf[1] + 64 * AP;
    Sf[3] = Sf[2] + 64 * AP;
    float* cr[4];
    cr[0] = Sf[3] + 64 * AP;
    cr[1] = cr[0] + 64;
    cr[2] = cr[1] + 64;
    cr[3] = cr[2] + 64;

    const int tid  = threadIdx.x;
    const int lane = tid & 31;
    const int w    = tid >> 5;
    const int lr   = lane >> 2;
    const int lc   = lane & 3;
    const int wm   = (w >> 1) * 16;
    const int wnq  = (w & 1) * 32;
    const int wnp  = (w & 1) * 40;

    const int by  = blockIdx.y;
    const int b   = by >> 3;
    const int kvh = by & 7;
    const int h0  = kvh * G_;
    const int q0  = (int)(gridDim.x - 1 - blockIdx.x) * 64;
    const float rscale = 0.11180339887498949f;

    float4 kreg[5], vreg[5];

    auto load_kv = [&](int kt) {
        #pragma unroll
        for (int j = 0; j < 5; j++) {
            int i = tid + j * 256;
            int r = i / 20, c4 = (i % 20) * 4;
            size_t base = ((size_t)(b * S_ + kt + r)) * (KV_ * D_) + kvh * D_ + c4;
            kreg[j] = *(const float4*)(K + base);
            vreg[j] = *(const float4*)(V + base);
        }
    };
    auto split_kv = [&]() {
        #pragma unroll
        for (int j = 0; j < 5; j++) {
            int i = tid + j * 256;
            int r = i / 20, c4 = (i % 20) * 4;
            float4 kv = kreg[j], vv = vreg[j];
            *(uint2*)(Khh + r * AQH + c4) = make_uint2(
                h2u(__float2half_rn(kv.x), __float2half_rn(kv.y)),
                h2u(__float2half_rn(kv.z), __float2half_rn(kv.w)));
            Vt[(c4 + 0) * VTS + r] = __float2half_rn(vv.x);
            Vt[(c4 + 1) * VTS + r] = __float2half_rn(vv.y);
            Vt[(c4 + 2) * VTS + r] = __float2half_rn(vv.z);
            Vt[(c4 + 3) * VTS + r] = __float2half_rn(vv.w);
        }
    };

    load_kv(0);

    // Q: fused rope + scale + fp16 for all 4 heads
    for (int i = tid; i < 4 * 64 * 10; i += 256) {
        int p  = i % 10;
        int t2 = i / 10;
        int r  = t2 % 64;
        int hh = t2 / 64;
        int d  = p * 4;
        const float* qb = Q + ((size_t)(b * S_ + q0 + r)) * (H_ * D_)
                            + (h0 + hh) * D_;
        float4 x1 = *(const float4*)(qb + d);
        float4 x2 = *(const float4*)(qb + d + 40);
        const float* cb = cosg + (size_t)(q0 + r) * D_;
        const float* sb = sing + (size_t)(q0 + r) * D_;
        float4 c1 = *(const float4*)(cb + d);
        float4 s1 = *(const float4*)(sb + d);
        float4 c2 = *(const float4*)(cb + d + 40);
        float4 s2 = *(const float4*)(sb + d + 40);
        float y1x = (x1.x * c1.x - x2.x * s1.x) * rscale;
        float y1y = (x1.y * c1.y - x2.y * s1.y) * rscale;
        float y1z = (x1.z * c1.z - x2.z * s1.z) * rscale;
        float y1w = (x1.w * c1.w - x2.w * s1.w) * rscale;
        float y2x = (x2.x * c2.x + x1.x * s2.x) * rscale;
        float y2y = (x2.y * c2.y + x1.y * s2.y) * rscale;
        float y2z = (x2.z * c2.z + x1.z * s2.z) * rscale;
        float y2w = (x2.w * c2.w + x1.w * s2.w) * rscale;
        __half* qh = Qh[hh];
        *(uint2*)(qh + r * AQH + d) = make_uint2(
            h2u(__float2half_rn(y1x), __float2half_rn(y1y)),
            h2u(__float2half_rn(y1z), __float2half_rn(y1w)));
        *(uint2*)(qh + r * AQH + d + 40) = make_uint2(
            h2u(__float2half_rn(y2x), __float2half_rn(y2y)),
            h2u(__float2half_rn(y2z), __float2half_rn(y2w)));
    }
    split_kv();

    const int myrow = tid >> 2;
    const int myg   = tid & 3;
    float mm[4] = {-1e30f, -1e30f, -1e30f, -1e30f};
    float ll[4] = {0.f, 0.f, 0.f, 0.f};

    float co[4][5][4];
    #pragma unroll
    for (int hh = 0; hh < 4; hh++)
        #pragma unroll
        for (int nj = 0; nj < 5; nj++)
            #pragma unroll
            for (int u = 0; u < 4; u++) co[hh][nj][u] = 0.f;

    for (int k0 = 0; k0 <= q0; k0 += 64) {
        __syncthreads();

        #pragma unroll
        for (int hh = 0; hh < 4; hh++) {
            const __half* Qhp = Qh[hh];
            float* Ps = Sf[hh];

            float cq[4][4];
            #pragma unroll
            for (int nj = 0; nj < 4; nj++)
                #pragma unroll
                for (int u = 0; u < 4; u++) cq[nj][u] = 0.f;

            #pragma unroll
            for (int ks = 0; ks < 5; ks++) {
                const int ko = ks * 16 + 2 * lc;
                unsigned ah[4];
                ah[0] = *(const unsigned*)&Qhp[(wm + lr) * AQH + ko];
                ah[1] = *(const unsigned*)&Qhp[(wm + lr + 8) * AQH + ko];
                ah[2] = *(const unsigned*)&Qhp[(wm + lr) * AQH + ko + 8];
                ah[3] = *(const unsigned*)&Qhp[(wm + lr + 8) * AQH + ko + 8];
                #pragma unroll
                for (int nj = 0; nj < 4; nj++) {
                    int cn = wnq + nj * 8 + lr;
                    unsigned bh_[2];
                    bh_[0] = *(const unsigned*)&Khh[cn * AQH + ko];
                    bh_[1] = *(const unsigned*)&Khh[cn * AQH + ko + 8];
                    mma_f16(cq[nj], ah, bh_);
                }
            }

            #pragma unroll
            for (int nj = 0; nj < 4; nj++) {
                int col = wnq + nj * 8 + 2 * lc;
                int r0 = wm + lr, r1 = wm + lr + 8;
                Ps[r0 * AP + col]     = (k0 + col     <= q0 + r0) ? cq[nj][0] : -1e30f;
                Ps[r0 * AP + col + 1] = (k0 + col + 1 <= q0 + r0) ? cq[nj][1] : -1e30f;
                Ps[r1 * AP + col]     = (k0 + col     <= q0 + r1) ? cq[nj][2] : -1e30f;
                Ps[r1 * AP + col + 1] = (k0 + col + 1 <= q0 + r1) ? cq[nj][3] : -1e30f;
            }
        }
        __syncthreads();

        const int kn = k0 + 64;
        const bool more = (kn <= q0);
        if (more) load_kv(kn);

        #pragma unroll
        for (int hh = 0; hh < 4; hh++) {
            float* Ps = Sf[hh];
            __half* Pmp = Pm[hh];
            float s[16];
            #pragma unroll
            for (int j4 = 0; j4 < 4; j4++) {
                float4 v4 = *(const float4*)(Ps + myrow * AP + myg * 16 + j4 * 4);
                s[j4 * 4 + 0] = v4.x; s[j4 * 4 + 1] = v4.y;
                s[j4 * 4 + 2] = v4.z; s[j4 * 4 + 3] = v4.w;
            }
            float mx = s[0];
            #pragma unroll
            for (int j = 1; j < 16; j++) mx = fmaxf(mx, s[j]);
            mx = fmaxf(mx, __shfl_xor_sync(0xffffffffu, mx, 1));
            mx = fmaxf(mx, __shfl_xor_sync(0xffffffffu, mx, 2));
            float mnew = fmaxf(mm[hh], mx);
            float corr = __expf(mm[hh] - mnew);
            float rs = 0.f;
            #pragma unroll
            for (int j = 0; j < 16; j += 2) {
                float p0 = __expf(s[j] - mnew);
                float p1 = __expf(s[j + 1] - mnew);
                rs += p0 + p1;
                *(__half2*)(Pmp + myrow * APH + myg * 16 + j) =
                    __floats2half2_rn(p0, p1);
            }
            rs += __shfl_xor_sync(0xffffffffu, rs, 1);
            rs += __shfl_xor_sync(0xffffffffu, rs, 2);
            mm[hh] = mnew;
            ll[hh] = ll[hh] * corr + rs;
            if (myg == 0) cr[hh][myrow] = corr;
        }
        __syncthreads();

        #pragma unroll
        for (int hh = 0; hh < 4; hh++) {
            const __half* Pmp = Pm[hh];
            float c0 = cr[hh][wm + lr], c1 = cr[hh][wm + lr + 8];
            #pragma unroll
            for (int nj = 0; nj < 5; nj++) {
                co[hh][nj][0] *= c0; co[hh][nj][1] *= c0;
                co[hh][nj][2] *= c1; co[hh][nj][3] *= c1;
            }
            #pragma unroll
            for (int ks = 0; ks < 4; ks++) {
                const int ko = ks * 16 + 2 * lc;
                unsigned a[4];
                a[0] = *(const unsigned*)&Pmp[(wm + lr) * APH + ko];
                a[1] = *(const unsigned*)&Pmp[(wm + lr + 8) * APH + ko];
                a[2] = *(const unsigned*)&Pmp[(wm + lr) * APH + ko + 8];
                a[3] = *(const unsigned*)&Pmp[(wm + lr + 8) * APH + ko + 8];
                #pragma unroll
                for (int nj = 0; nj < 5; nj++) {
                    int cn = wnp + nj * 8 + lr;
                    unsigned bb[2];
                    bb[0] = *(const unsigned*)&Vt[cn * VTS + ko];
                    bb[1] = *(const unsigned*)&Vt[cn * VTS + ko + 8];
                    mma_f16(co[hh][nj], a, bb);
                }
            }
        }
        __syncthreads();

        if (more) split_kv();
    }

    if (myg == 0) {
        #pragma unroll
        for (int hh = 0; hh < 4; hh++) cr[hh][myrow] = 1.f / ll[hh];
    }
    __syncthreads();
    #pragma unroll
    for (int hh = 0; hh < 4; hh++) {
        float i0 = cr[hh][wm + lr], i1 = cr[hh][wm + lr + 8];
        size_t ro0 = ((size_t)(b * S_ + q0 + wm + lr)) * (H_ * D_) + (h0 + hh) * D_;
        size_t ro1 = ((size_t)(b * S_ + q0 + wm + lr + 8)) * (H_ * D_) + (h0 + hh) * D_;
        #pragma unroll
        for (int nj = 0; nj < 5; nj++) {
            int col = wnp + nj * 8 + 2 * lc;
            *(__half2*)(O + ro0 + col) =
                __floats2half2_rn(co[hh][nj][0] * i0, co[hh][nj][1] * i0);
            *(__half2*)(O + ro1 + col) =
                __floats2half2_rn(co[hh][nj][2] * i1, co[hh][nj][3] * i1);
        }
    }
}

// ---------------------------------------------------------------------------
// Launch
// ---------------------------------------------------------------------------
extern "C" void kernel_launch(void* const* d_in, const int* in_sizes, int n_in,
                              void* d_out, int out_size)
{
    const float* hs   = (const float*)d_in[0];
    const float* cosf = (const float*)d_in[1];
    const float* sinf = (const float*)d_in[2];
    const float* Wq   = (const float*)d_in[3];
    const float* Wk   = (const float*)d_in[4];
    const float* Wv   = (const float*)d_in[5];
    const float* Wo   = (const float*)d_in[6];
    float* out = (float*)d_out;

    float *Qp, *Kp, *Vp;
    __half *Cph, *HSh, *WqT, *WkT, *WvT, *WoT;
    cudaGetSymbolAddress((void**)&Qp,  g_Q);
    cudaGetSymbolAddress((void**)&Kp,  g_K);
    cudaGetSymbolAddress((void**)&Vp,  g_V);
    cudaGetSymbolAddress((void**)&Cph, g_ctx_h);
    cudaGetSymbolAddress((void**)&HSh, g_hs_h);
    cudaGetSymbolAddress((void**)&WqT, g_WqT);
    cudaGetSymbolAddress((void**)&WkT, g_WkT);
    cudaGetSymbolAddress((void**)&WvT, g_WvT);
    cudaGetSymbolAddress((void**)&WoT, g_WoT);

    // Persistent-grid size: 2 CTAs per SM
    int nsm = 148;
    cudaDeviceGetAttribute(&nsm, cudaDevAttrMultiProcessorCount, 0);
    const int pgrid = 2 * nsm;

    // Pre-passes
    {
        int n4 = (int)((size_t)BS_ * HID_ / 4);
        convert_half<<<(n4 + 255) / 256, 256>>>(
            (const float4*)hs, (__half2*)HSh, n4);
        dim3 tb(32, 8);
        transpose_h<<<dim3(HID_ / 32, HID_ / 32), tb>>>(Wq, WqT, HID_, HID_);
        transpose_h<<<dim3((KV_ * D_) / 32, HID_ / 32), tb>>>(Wk, WkT, HID_, KV_ * D_);
        transpose_h<<<dim3((KV_ * D_) / 32, HID_ / 32), tb>>>(Wv, WvT, HID_, KV_ * D_);
        transpose_h<<<dim3(HID_ / 32, HID_ / 32), tb>>>(Wo, WoT, HID_, HID_);
    }

    cudaFuncSetAttribute(gemm_qkv_persist,
                         cudaFuncAttributeMaxDynamicSharedMemorySize, GEMM_SMEM);
    cudaFuncSetAttribute(gemm_h_persist,
                         cudaFuncAttributeMaxDynamicSharedMemorySize, GEMM_SMEM);

    // Fused QKV projection (fp16, 3-stage, persistent)
    gemm_qkv_persist<<<pgrid, 256, GEMM_SMEM>>>(HSh, WqT, Qp, WkT, Kp, WvT, Vp);

    // RoPE on K only
    {
        size_t tk = (size_t)BS_ * KV_ * 40;
        rope_kernel<<<(unsigned)((tk + 255) / 256), 256>>>(Kp, cosf, sinf, KV_, tk);
    }

    // Attention: 4 heads per block, fused Q-rope, LPT block order
    {
        const int smem =
            (5 * 64 * AQH + 80 * VTS + 4 * 64 * APH) * 2
          + (4 * 64 * AP + 4 * 64) * 4;
        cudaFuncSetAttribute(attn_mma4,
                             cudaFuncAttributeMaxDynamicSharedMemorySize, smem);
        dim3 ga(S_ / 64, B_ * KV_);
        attn_mma4<<<ga, 256, smem>>>(Qp, Kp, Vp, Cph, cosf, sinf);
    }

    // Output projection (fp16, 3-stage, persistent)
    gemm_h_persist<<<pgrid, 256, GEMM_SMEM>>>(Cph, WoT, out);
}

// round 17
// speedup vs baseline: 1.0636x; 1.0636x over previous
#include <cuda_runtime.h>
#include <cuda_fp16.h>
#include <math.h>

// Problem constants
#define B_   2
#define S_   2048
#define HID_ 2560
#define H_   32
#define KV_  8
#define D_   80
#define G_   4
#define BS_  (B_*S_)      // 4096 total rows

// Scratch (device globals)
__device__ float  g_Q[(size_t)BS_ * H_ * D_];
__device__ float  g_K[(size_t)BS_ * KV_ * D_];
__device__ float  g_V[(size_t)BS_ * KV_ * D_];
__device__ __half g_ctx_h[(size_t)BS_ * H_ * D_];
__device__ __half g_hs_h[(size_t)BS_ * HID_];
__device__ __half g_WqT[(size_t)HID_ * H_ * D_];   // [N=2560][K=2560]
__device__ __half g_WkT[(size_t)KV_ * D_ * HID_];  // [640][2560]
__device__ __half g_WvT[(size_t)KV_ * D_ * HID_];
__device__ __half g_WoT[(size_t)HID_ * H_ * D_];   // [2560][2560]

// ---------------------------------------------------------------------------
// Helpers
// ---------------------------------------------------------------------------
__device__ __forceinline__ unsigned smem_u32(const void* p) {
    return (unsigned)__cvta_generic_to_shared(p);
}
__device__ __forceinline__ void cp_async16(unsigned dst, const void* src) {
    asm volatile("cp.async.cg.shared.global [%0], [%1], 16;\n"
                 :: "r"(dst), "l"(src));
}
#define CP_COMMIT() asm volatile("cp.async.commit_group;\n" ::: "memory")
#define CP_WAIT1()  asm volatile("cp.async.wait_group 1;\n" ::: "memory")

__device__ __forceinline__ void mma_f16(float* c, const unsigned* a, const unsigned* b) {
    asm volatile(
        "mma.sync.aligned.m16n8k16.row.col.f32.f16.f16.f32 "
        "{%0,%1,%2,%3}, {%4,%5,%6,%7}, {%8,%9}, {%0,%1,%2,%3};\n"
        : "+f"(c[0]), "+f"(c[1]), "+f"(c[2]), "+f"(c[3])
        : "r"(a[0]), "r"(a[1]), "r"(a[2]), "r"(a[3]), "r"(b[0]), "r"(b[1]));
}

__device__ __forceinline__ void ldm_x4(unsigned& r0, unsigned& r1,
                                       unsigned& r2, unsigned& r3, unsigned addr) {
    asm volatile("ldmatrix.sync.aligned.m8n8.x4.shared.b16 {%0,%1,%2,%3}, [%4];"
                 : "=r"(r0), "=r"(r1), "=r"(r2), "=r"(r3) : "r"(addr));
}
__device__ __forceinline__ void ldm_x2(unsigned& r0, unsigned& r1, unsigned addr) {
    asm volatile("ldmatrix.sync.aligned.m8n8.x2.shared.b16 {%0,%1}, [%2];"
                 : "=r"(r0), "=r"(r1) : "r"(addr));
}

// ---------------------------------------------------------------------------
// Pre-passes: hs -> half ; weights -> transposed half [N][K]
// ---------------------------------------------------------------------------
__global__ void convert_half(const float4* __restrict__ in,
                             __half2* __restrict__ out, int n4)
{
    int i = blockIdx.x * blockDim.x + threadIdx.x;
    if (i < n4) {
        float4 v = in[i];
        out[2 * i]     = __floats2half2_rn(v.x, v.y);
        out[2 * i + 1] = __floats2half2_rn(v.z, v.w);
    }
}

__global__ void transpose_h(const float* __restrict__ W,
                            __half* __restrict__ WT, int Kd, int Nd)
{
    __shared__ float t[32][33];
    int n0 = blockIdx.x * 32, k0 = blockIdx.y * 32;
    int tx = threadIdx.x, ty = threadIdx.y;
    #pragma unroll
    for (int i = 0; i < 4; i++)
        t[ty + i * 8][tx] = W[(size_t)(k0 + ty + i * 8) * Nd + n0 + tx];
    __syncthreads();
    #pragma unroll
    for (int i = 0; i < 4; i++)
        WT[(size_t)(n0 + ty + i * 8) * Kd + k0 + tx] =
            __float2half_rn(t[tx][ty + i * 8]);
}

// ---------------------------------------------------------------------------
// FP16 tensor-core GEMM (round-11/15 proven config; fragment loads now via
// ldmatrix — bitwise-identical operand values, far fewer issue slots):
// 128x128 tile, BK=32 halves, 8 warps, 3-stage cp.async, 2 CTAs/SM.
// ---------------------------------------------------------------------------
#define HSTR 40
#define GSTG (128 * HSTR * 2)                    // halves per stage (A+B)
#define GEMM_SMEM (3 * GSTG * 2)                 // bytes = 61440

__device__ __forceinline__ void gemm_core_h(
    const __half* __restrict__ A, const __half* __restrict__ BT,
    float* __restrict__ C, int N, int K, int bm, int bn)
{
    extern __shared__ __half gsm[];

    const int tid  = threadIdx.x;
    const int lane = tid & 31;
    const int w    = tid >> 5;
    const int wm   = (w >> 2) * 64;
    const int wn   = (w & 3) * 32;
    const int lr   = lane >> 2;
    const int lc   = lane & 3;

    const int l_r = tid >> 2;
    const int l_c = (tid & 3) * 8;

    // ldmatrix lane addressing
    const int g    = lane >> 3;          // 0..3
    const int lrow = lane & 7;
    const int a_r0 = wm + ((g & 1) << 3) + lrow;   // + mi*16
    const int a_k0 = (g >> 1) << 3;                // + ks*16
    const int b_n0 = wn + ((g >> 1) << 3) + lrow;  // + p*16
    const int b_k0 = (g & 1) << 3;                 // + ks*16

    float acc[4][4][4];
    #pragma unroll
    for (int mi = 0; mi < 4; mi++)
        #pragma unroll
        for (int nj = 0; nj < 4; nj++)
            #pragma unroll
            for (int u = 0; u < 4; u++) acc[mi][nj][u] = 0.f;

    const int T = K / 32;

    auto load_tile = [&](int kt, int buf) {
        __half* as = gsm + buf * GSTG;
        __half* bs = as + 128 * HSTR;
        const __half* ag = A + (size_t)(bm + l_r) * K + kt * 32 + l_c;
        cp_async16(smem_u32(&as[l_r * HSTR + l_c]), ag);
        cp_async16(smem_u32(&as[(l_r + 64) * HSTR + l_c]), ag + (size_t)64 * K);
        const __half* bg = BT + (size_t)(bn + l_r) * K + kt * 32 + l_c;
        cp_async16(smem_u32(&bs[l_r * HSTR + l_c]), bg);
        cp_async16(smem_u32(&bs[(l_r + 64) * HSTR + l_c]), bg + (size_t)64 * K);
    };

    load_tile(0, 0); CP_COMMIT();
    load_tile(1, 1); CP_COMMIT();

    for (int kt = 0; kt < T; kt++) {
        const int buf = kt % 3;
        CP_WAIT1();
        __syncthreads();
        if (kt + 2 < T) load_tile(kt + 2, (kt + 2) % 3);
        CP_COMMIT();

        const __half* as = gsm + buf * GSTG;
        const __half* bs = as + 128 * HSTR;
        #pragma unroll
        for (int ks = 0; ks < 2; ks++) {
            const int ko = ks * 16;
            unsigned af[4][4], bf[4][2];
            #pragma unroll
            for (int mi = 0; mi < 4; mi++)
                ldm_x4(af[mi][0], af[mi][1], af[mi][2], af[mi][3],
                       smem_u32(&as[(a_r0 + mi * 16) * HSTR + ko + a_k0]));
            #pragma unroll
            for (int p = 0; p < 2; p++)
                ldm_x4(bf[2 * p][0], bf[2 * p][1], bf[2 * p + 1][0], bf[2 * p + 1][1],
                       smem_u32(&bs[(b_n0 + p * 16) * HSTR + ko + b_k0]));
            #pragma unroll
            for (int mi = 0; mi < 4; mi++)
                #pragma unroll
                for (int nj = 0; nj < 4; nj++)
                    mma_f16(acc[mi][nj], af[mi], bf[nj]);
        }
    }

    #pragma unroll
    for (int mi = 0; mi < 4; mi++) {
        int r0 = bm + wm + mi * 16 + lr;
        #pragma unroll
        for (int nj = 0; nj < 4; nj++) {
            int cn = bn + wn + nj * 8 + 2 * lc;
            *(float2*)&C[(size_t)r0 * N + cn] =
                make_float2(acc[mi][nj][0], acc[mi][nj][1]);
            *(float2*)&C[(size_t)(r0 + 8) * N + cn] =
                make_float2(acc[mi][nj][2], acc[mi][nj][3]);
        }
    }
}

__global__ __launch_bounds__(256, 2) void gemm_h(
    const __half* __restrict__ A, const __half* __restrict__ BT,
    float* __restrict__ C, int N, int K)
{
    gemm_core_h(A, BT, C, N, K, blockIdx.y * 128, blockIdx.x * 128);
}

__global__ __launch_bounds__(256, 2) void gemm_qkv_h(
    const __half* __restrict__ A,
    const __half* __restrict__ WqT, float* __restrict__ Qo,
    const __half* __restrict__ WkT, float* __restrict__ Ko,
    const __half* __restrict__ WvT, float* __restrict__ Vo)
{
    const int bx = blockIdx.x;
    const int bm = blockIdx.y * 128;
    if (bx < 20)       gemm_core_h(A, WqT, Qo, HID_,     HID_, bm, bx * 128);
    else if (bx < 25)  gemm_core_h(A, WkT, Ko, KV_ * D_, HID_, bm, (bx - 20) * 128);
    else               gemm_core_h(A, WvT, Vo, KV_ * D_, HID_, bm, (bx - 25) * 128);
}

// ---------------------------------------------------------------------------
// RoPE (in-place, fp32) — K only; Q's rope is fused into attention.
// ---------------------------------------------------------------------------
__global__ void rope_kernel(float* __restrict__ X,
                            const float* __restrict__ cosf,
                            const float* __restrict__ sinf,
                            int nheads, size_t total)
{
    size_t idx = (size_t)blockIdx.x * blockDim.x + threadIdx.x;
    if (idx >= total) return;
    int d = (int)(idx % 40);
    size_t t = idx / 40;
    int head = (int)(t % nheads);
    size_t row = t / nheads;
    int s = (int)(row % S_);

    float* base = X + row * ((size_t)nheads * D_) + (size_t)head * D_;
    float x1 = base[d];
    float x2 = base[d + 40];
    float c1 = cosf[(size_t)s * D_ + d];
    float s1 = sinf[(size_t)s * D_ + d];
    float c2 = cosf[(size_t)s * D_ + d + 40];
    float s2 = sinf[(size_t)s * D_ + d + 40];
    base[d]      = x1 * c1 - x2 * s1;
    base[d + 40] = x2 * c2 + x1 * s2;
}

// ---------------------------------------------------------------------------
// Flash attention (round-15 structure; fragment loads via ldmatrix):
// 4 heads/block, fused Q-rope, LPT order, fp16 single-term QK/PV,
// register-staged K/V prefetch, 4 barriers/ktile.
// ---------------------------------------------------------------------------
#define AQH 88
#define VTS 72
#define APH 72
#define AP  68

__device__ __forceinline__ unsigned h2u(__half a, __half b) {
    __half2 p = __halves2half2(a, b);
    return *(unsigned*)&p;
}

__global__ __launch_bounds__(256, 1) void attn_mma4(
    const float* __restrict__ Q, const float* __restrict__ K,
    const float* __restrict__ V, __half* __restrict__ O,
    const float* __restrict__ cosg, const float* __restrict__ sing)
{
    extern __shared__ char smb[];
    __half* Qh[4];
    Qh[0] = (__half*)smb;
    Qh[1] = Qh[0] + 64 * AQH;
    Qh[2] = Qh[1] + 64 * AQH;
    Qh[3] = Qh[2] + 64 * AQH;
    __half* Khh = Qh[3] + 64 * AQH;
    __half* Vt  = Khh + 64 * AQH;
    __half* Pm[4];
    Pm[0] = Vt + 80 * VTS;
    Pm[1] = Pm[0] + 64 * APH;
    Pm[2] = Pm[1] + 64 * APH;
    Pm[3] = Pm[2] + 64 * APH;
    float* Sf[4];
    Sf[0] = (float*)(Pm[3] + 64 * APH);
    Sf[1] = Sf[0] + 64 * AP;
    Sf[2] = Sf[1] + 64 * AP;
    Sf[3] = Sf[2] + 64 * AP;
    float* cr[4];
    cr[0] = Sf[3] + 64 * AP;
    cr[1] = cr[0] + 64;
    cr[2] = cr[1] + 64;
    cr[3] = cr[2] + 64;

    const int tid  = threadIdx.x;
    const int lane = tid & 31;
    const int w    = tid >> 5;
    const int lr   = lane >> 2;
    const int lc   = lane & 3;
    const int wm   = (w >> 1) * 16;
    const int wnq  = (w & 1) * 32;
    const int wnp  = (w & 1) * 40;

    // ldmatrix lane addressing
    const int g    = lane >> 3;
    const int lrow = lane & 7;
    const int aq_r = wm + ((g & 1) << 3) + lrow;    // A rows (QK & PV)
    const int aq_k = (g >> 1) << 3;
    const int bq_n = wnq + ((g >> 1) << 3) + lrow;  // QK B rows (+p*16)
    const int bq_k = (g & 1) << 3;
    const int bv_n = wnp + ((g >> 1) << 3) + lrow;  // PV B rows (+p*16)
    const int bv_n2 = wnp + 32 + lrow;              // PV B nj=4 tile
    const int bv_k2 = ((lane >> 3) & 1) << 3;

    const int by  = blockIdx.y;
    const int b   = by >> 3;
    const int kvh = by & 7;
    const int h0  = kvh * G_;
    const int q0  = (int)(gridDim.x - 1 - blockIdx.x) * 64;
    const float rscale = 0.11180339887498949f;

    float4 kreg[5], vreg[5];

    auto load_kv = [&](int kt) {
        #pragma unroll
        for (int j = 0; j < 5; j++) {
            int i = tid + j * 256;
            int r = i / 20, c4 = (i % 20) * 4;
            size_t base = ((size_t)(b * S_ + kt + r)) * (KV_ * D_) + kvh * D_ + c4;
            kreg[j] = *(const float4*)(K + base);
            vreg[j] = *(const float4*)(V + base);
        }
    };
    auto split_kv = [&]() {
        #pragma unroll
        for (int j = 0; j < 5; j++) {
            int i = tid + j * 256;
            int r = i / 20, c4 = (i % 20) * 4;
            float4 kv = kreg[j], vv = vreg[j];
            *(uint2*)(Khh + r * AQH + c4) = make_uint2(
                h2u(__float2half_rn(kv.x), __float2half_rn(kv.y)),
                h2u(__float2half_rn(kv.z), __float2half_rn(kv.w)));
            Vt[(c4 + 0) * VTS + r] = __float2half_rn(vv.x);
            Vt[(c4 + 1) * VTS + r] = __float2half_rn(vv.y);
            Vt[(c4 + 2) * VTS + r] = __float2half_rn(vv.z);
            Vt[(c4 + 3) * VTS + r] = __float2half_rn(vv.w);
        }
    };

    load_kv(0);

    // Q: fused rope + scale + fp16 for all 4 heads
    for (int i = tid; i < 4 * 64 * 10; i += 256) {
        int p  = i % 10;
        int t2 = i / 10;
        int r  = t2 % 64;
        int hh = t2 / 64;
        int d  = p * 4;
        const float* qb = Q + ((size_t)(b * S_ + q0 + r)) * (H_ * D_)
                            + (h0 + hh) * D_;
        float4 x1 = *(const float4*)(qb + d);
        float4 x2 = *(const float4*)(qb + d + 40);
        const float* cb = cosg + (size_t)(q0 + r) * D_;
        const float* sb = sing + (size_t)(q0 + r) * D_;
        float4 c1 = *(const float4*)(cb + d);
        float4 s1 = *(const float4*)(sb + d);
        float4 c2 = *(const float4*)(cb + d + 40);
        float4 s2 = *(const float4*)(sb + d + 40);
        float y1x = (x1.x * c1.x - x2.x * s1.x) * rscale;
        float y1y = (x1.y * c1.y - x2.y * s1.y) * rscale;
        float y1z = (x1.z * c1.z - x2.z * s1.z) * rscale;
        float y1w = (x1.w * c1.w - x2.w * s1.w) * rscale;
        float y2x = (x2.x * c2.x + x1.x * s2.x) * rscale;
        float y2y = (x2.y * c2.y + x1.y * s2.y) * rscale;
        float y2z = (x2.z * c2.z + x1.z * s2.z) * rscale;
        float y2w = (x2.w * c2.w + x1.w * s2.w) * rscale;
        __half* qh = Qh[hh];
        *(uint2*)(qh + r * AQH + d) = make_uint2(
            h2u(__float2half_rn(y1x), __float2half_rn(y1y)),
            h2u(__float2half_rn(y1z), __float2half_rn(y1w)));
        *(uint2*)(qh + r * AQH + d + 40) = make_uint2(
            h2u(__float2half_rn(y2x), __float2half_rn(y2y)),
            h2u(__float2half_rn(y2z), __float2half_rn(y2w)));
    }
    split_kv();

    const int myrow = tid >> 2;
    const int myg   = tid & 3;
    float mm[4] = {-1e30f, -1e30f, -1e30f, -1e30f};
    float ll[4] = {0.f, 0.f, 0.f, 0.f};

    float co[4][5][4];
    #pragma unroll
    for (int hh = 0; hh < 4; hh++)
        #pragma unroll
        for (int nj = 0; nj < 5; nj++)
            #pragma unroll
            for (int u = 0; u < 4; u++) co[hh][nj][u] = 0.f;

    for (int k0 = 0; k0 <= q0; k0 += 64) {
        __syncthreads();

        // QK^T (fp16, single-term, ldmatrix) for all heads
        #pragma unroll
        for (int hh = 0; hh < 4; hh++) {
            const __half* Qhp = Qh[hh];
            float* Ps = Sf[hh];

            float cq[4][4];
            #pragma unroll
            for (int nj = 0; nj < 4; nj++)
                #pragma unroll
                for (int u = 0; u < 4; u++) cq[nj][u] = 0.f;

            #pragma unroll
            for (int ks = 0; ks < 5; ks++) {
                const int ko = ks * 16;
                unsigned ah[4], bh[4][2];
                ldm_x4(ah[0], ah[1], ah[2], ah[3],
                       smem_u32(&Qhp[aq_r * AQH + ko + aq_k]));
                #pragma unroll
                for (int p = 0; p < 2; p++)
                    ldm_x4(bh[2 * p][0], bh[2 * p][1],
                           bh[2 * p + 1][0], bh[2 * p + 1][1],
                           smem_u32(&Khh[(bq_n + p * 16) * AQH + ko + bq_k]));
                #pragma unroll
                for (int nj = 0; nj < 4; nj++)
                    mma_f16(cq[nj], ah, bh[nj]);
            }

            #pragma unroll
            for (int nj = 0; nj < 4; nj++) {
                int col = wnq + nj * 8 + 2 * lc;
                int r0 = wm + lr, r1 = wm + lr + 8;
                Ps[r0 * AP + col]     = (k0 + col     <= q0 + r0) ? cq[nj][0] : -1e30f;
                Ps[r0 * AP + col + 1] = (k0 + col + 1 <= q0 + r0) ? cq[nj][1] : -1e30f;
                Ps[r1 * AP + col]     = (k0 + col     <= q0 + r1) ? cq[nj][2] : -1e30f;
                Ps[r1 * AP + col + 1] = (k0 + col + 1 <= q0 + r1) ? cq[nj][3] : -1e30f;
            }
        }
        __syncthreads();

        const int kn = k0 + 64;
        const bool more = (kn <= q0);
        if (more) load_kv(kn);

        // Online softmax (fp32 -> fp16 P), all heads
        #pragma unroll
        for (int hh = 0; hh < 4; hh++) {
            float* Ps = Sf[hh];
            __half* Pmp = Pm[hh];
            float s[16];
            #pragma unroll
            for (int j4 = 0; j4 < 4; j4++) {
                float4 v4 = *(const float4*)(Ps + myrow * AP + myg * 16 + j4 * 4);
                s[j4 * 4 + 0] = v4.x; s[j4 * 4 + 1] = v4.y;
                s[j4 * 4 + 2] = v4.z; s[j4 * 4 + 3] = v4.w;
            }
            float mx = s[0];
            #pragma unroll
            for (int j = 1; j < 16; j++) mx = fmaxf(mx, s[j]);
            mx = fmaxf(mx, __shfl_xor_sync(0xffffffffu, mx, 1));
            mx = fmaxf(mx, __shfl_xor_sync(0xffffffffu, mx, 2));
            float mnew = fmaxf(mm[hh], mx);
            float corr = __expf(mm[hh] - mnew);
            float rs = 0.f;
            #pragma unroll
            for (int j = 0; j < 16; j += 2) {
                float p0 = __expf(s[j] - mnew);
                float p1 = __expf(s[j + 1] - mnew);
                rs += p0 + p1;
                *(__half2*)(Pmp + myrow * APH + myg * 16 + j) =
                    __floats2half2_rn(p0, p1);
            }
            rs += __shfl_xor_sync(0xffffffffu, rs, 1);
            rs += __shfl_xor_sync(0xffffffffu, rs, 2);
            mm[hh] = mnew;
            ll[hh] = ll[hh] * corr + rs;
            if (myg == 0) cr[hh][myrow] = corr;
        }
        __syncthreads();

        // Rescale + PV (fp16 single-term, ldmatrix), all heads
        #pragma unroll
        for (int hh = 0; hh < 4; hh++) {
            const __half* Pmp = Pm[hh];
            float c0 = cr[hh][wm + lr], c1 = cr[hh][wm + lr + 8];
            #pragma unroll
            for (int nj = 0; nj < 5; nj++) {
                co[hh][nj][0] *= c0; co[hh][nj][1] *= c0;
                co[hh][nj][2] *= c1; co[hh][nj][3] *= c1;
            }
            #pragma unroll
            for (int ks = 0; ks < 4; ks++) {
                const int ko = ks * 16;
                unsigned a[4], bb[5][2];
                ldm_x4(a[0], a[1], a[2], a[3],
                       smem_u32(&Pmp[aq_r * APH + ko + aq_k]));
                #pragma unroll
                for (int p = 0; p < 2; p++)
                    ldm_x4(bb[2 * p][0], bb[2 * p][1],
                           bb[2 * p + 1][0], bb[2 * p + 1][1],
                           smem_u32(&Vt[(bv_n + p * 16) * VTS + ko + bq_k]));
                ldm_x2(bb[4][0], bb[4][1],
                       smem_u32(&Vt[bv_n2 * VTS + ko + bv_k2]));
                #pragma unroll
                for (int nj = 0; nj < 5; nj++)
                    mma_f16(co[hh][nj], a, bb[nj]);
            }
        }
        __syncthreads();

        if (more) split_kv();
    }

    if (myg == 0) {
        #pragma unroll
        for (int hh = 0; hh < 4; hh++) cr[hh][myrow] = 1.f / ll[hh];
    }
    __syncthreads();
    #pragma unroll
    for (int hh = 0; hh < 4; hh++) {
        float i0 = cr[hh][wm + lr], i1 = cr[hh][wm + lr + 8];
        size_t ro0 = ((size_t)(b * S_ + q0 + wm + lr)) * (H_ * D_) + (h0 + hh) * D_;
        size_t ro1 = ((size_t)(b * S_ + q0 + wm + lr + 8)) * (H_ * D_) + (h0 + hh) * D_;
        #pragma unroll
        for (int nj = 0; nj < 5; nj++) {
            int col = wnp + nj * 8 + 2 * lc;
            *(__half2*)(O + ro0 + col) =
                __floats2half2_rn(co[hh][nj][0] * i0, co[hh][nj][1] * i0);
            *(__half2*)(O + ro1 + col) =
                __floats2half2_rn(co[hh][nj][2] * i1, co[hh][nj][3] * i1);
        }
    }
}

// ---------------------------------------------------------------------------
// Launch
// ---------------------------------------------------------------------------
extern "C" void kernel_launch(void* const* d_in, const int* in_sizes, int n_in,
                              void* d_out, int out_size)
{
    const float* hs   = (const float*)d_in[0];
    const float* cosf = (const float*)d_in[1];
    const float* sinf = (const float*)d_in[2];
    const float* Wq   = (const float*)d_in[3];
    const float* Wk   = (const float*)d_in[4];
    const float* Wv   = (const float*)d_in[5];
    const float* Wo   = (const float*)d_in[6];
    float* out = (float*)d_out;

    float *Qp, *Kp, *Vp;
    __half *Cph, *HSh, *WqT, *WkT, *WvT, *WoT;
    cudaGetSymbolAddress((void**)&Qp,  g_Q);
    cudaGetSymbolAddress((void**)&Kp,  g_K);
    cudaGetSymbolAddress((void**)&Vp,  g_V);
    cudaGetSymbolAddress((void**)&Cph, g_ctx_h);
    cudaGetSymbolAddress((void**)&HSh, g_hs_h);
    cudaGetSymbolAddress((void**)&WqT, g_WqT);
    cudaGetSymbolAddress((void**)&WkT, g_WkT);
    cudaGetSymbolAddress((void**)&WvT, g_WvT);
    cudaGetSymbolAddress((void**)&WoT, g_WoT);

    // Pre-passes
    {
        int n4 = (int)((size_t)BS_ * HID_ / 4);
        convert_half<<<(n4 + 255) / 256, 256>>>(
            (const float4*)hs, (__half2*)HSh, n4);
        dim3 tb(32, 8);
        transpose_h<<<dim3(HID_ / 32, HID_ / 32), tb>>>(Wq, WqT, HID_, HID_);
        transpose_h<<<dim3((KV_ * D_) / 32, HID_ / 32), tb>>>(Wk, WkT, HID_, KV_ * D_);
        transpose_h<<<dim3((KV_ * D_) / 32, HID_ / 32), tb>>>(Wv, WvT, HID_, KV_ * D_);
        transpose_h<<<dim3(HID_ / 32, HID_ / 32), tb>>>(Wo, WoT, HID_, HID_);
    }

    cudaFuncSetAttribute(gemm_qkv_h,
                         cudaFuncAttributeMaxDynamicSharedMemorySize, GEMM_SMEM);
    cudaFuncSetAttribute(gemm_h,
                         cudaFuncAttributeMaxDynamicSharedMemorySize, GEMM_SMEM);

    // Fused QKV projection (fp16, 3-stage)
    {
        dim3 g(30, BS_ / 128);
        gemm_qkv_h<<<g, 256, GEMM_SMEM>>>(HSh, WqT, Qp, WkT, Kp, WvT, Vp);
    }

    // RoPE on K only
    {
        size_t tk = (size_t)BS_ * KV_ * 40;
        rope_kernel<<<(unsigned)((tk + 255) / 256), 256>>>(Kp, cosf, sinf, KV_, tk);
    }

    // Attention: 4 heads per block, fused Q-rope, LPT block order
    {
        const int smem =
            (5 * 64 * AQH + 80 * VTS + 4 * 64 * APH) * 2
          + (4 * 64 * AP + 4 * 64) * 4;
        cudaFuncSetAttribute(attn_mma4,
                             cudaFuncAttributeMaxDynamicSharedMemorySize, smem);
        dim3 ga(S_ / 64, B_ * KV_);
        attn_mma4<<<ga, 256, smem>>>(Qp, Kp, Vp, Cph, cosf, sinf);
    }

    // Output projection (fp16, 3-stage)
    {
        dim3 go(HID_ / 128, BS_ / 128);
        gemm_h<<<go, 256, GEMM_SMEM>>>(Cph, WoT, out, HID_, HID_);
    }
}